// round 5
// baseline (speedup 1.0000x reference)
#include <cuda_runtime.h>
#include <cstdint>

// NMS_20933670600803
// heatmap: (B, 1, 14, 14) float32, B = 131072 -> out = [m1 | m2] float32.
//
// One warp per item; lane owns elements i = lane + 32k, k < 7 (i < 196).
//
// Keys: v > 0.6  ->  key = (fb - bits(0.6f))<<8 | (255 - i)   (computed mod 2^32
//        via IMNMX + IMAD with a precomputed bias; exact, monotone, tie->min idx)
//        v <= 0.6 / suppressed -> key = 255 - i.
// Warp argmax = one REDUX.MAX.U32. Suppression = key &= 0xFF.
//
// Window test (clamps provably no-ops for coords in [0,13]):
//   inwin <=> (eu-x+5)(x+4-eu) >= 0 && (ev-y+5)(y+4-ev) >= 0
// evaluated in exact float FMA (fma pipe), sign-combined with 3 ALU ops.
//
// Voronoi: d1<d2 <=> Cx*u + Cy*v - Cc < 0, exact float FMA, sign bit -> 1.0f.

#define NPIX 196
#define WPB  8
#define THREADS (WPB * 32)
#define KTHR 0x3F19999Au        // __float_as_uint(0.6f)

__global__ __launch_bounds__(THREADS)
void nms_masks_kernel(const float* __restrict__ hm,
                      float* __restrict__ out,
                      int B)
{
    const int warp = blockIdx.x * WPB + (threadIdx.x >> 5);
    const int lane = threadIdx.x & 31;
    if (warp >= B) return;

    const float* __restrict__ p = hm + (size_t)warp * NPIX;

    unsigned key[7];
    float feu[7], fev[7];
    const bool live6 = (lane < 4);                      // k=6 valid only for i<196
    // kbase = 255 - lane - ((KTHR*256) mod 2^32); KTHR<<8 mod 2^32 = 0x19999A00
    const unsigned kbase = 0xE66666FFu - (unsigned)lane;

#pragma unroll
    for (int k = 0; k < 7; k++) {
        const int i = lane + 32 * k;
        const bool live = (k < 6) || live6;
        unsigned fb = 0u;
        if (live) fb = __float_as_uint(__ldg(p + i));
        const unsigned M = (fb > KTHR) ? fb : KTHR;     // IMNMX.U32
        const unsigned kv = M * 256u + (kbase - 32u * (unsigned)k);  // IMAD, wraps ok
        key[k] = live ? kv : 0u;
        const int eu = i / 14;
        const int ev = i - 14 * eu;
        feu[k] = (float)eu;
        fev[k] = (float)ev;
    }

    int px[4], py[4];

#pragma unroll
    for (int it = 0; it < 4; it++) {
        // local max (6 IMNMX.U32), then one REDUX.MAX.U32 broadcast
        unsigned m = max(max(max(key[0], key[1]), max(key[2], key[3])),
                         max(max(key[4], key[5]), key[6]));
        const unsigned w = __reduce_max_sync(0xffffffffu, m);

        const int bi = 255 - (int)(w & 0xFFu);
        const int x  = bi / 14;
        const int y  = bi - 14 * x;
        px[it] = x; py[it] = y;

        if (it < 3) {                                   // no suppression needed after last peak
            const float xf = (float)x, yf = (float)y;
            const float sx  = 2.0f * xf - 1.0f;         // (eu-x+5)(x+4-eu) = eu*(sx-eu)+cxn
            const float cxn = fmaf(xf, 1.0f - xf, 20.0f);
            const float sy  = 2.0f * yf - 1.0f;
            const float cyn = fmaf(yf, 1.0f - yf, 20.0f);
#pragma unroll
            for (int k = 0; k < 7; k++) {
                const float pr = fmaf(feu[k], sx - feu[k], cxn);   // >=0 iff row in window
                const float pc = fmaf(fev[k], sy - fev[k], cyn);   // >=0 iff col in window
                const unsigned s = __float_as_uint(pr) | __float_as_uint(pc);
                // inwin: both signs 0 -> sra=0 -> key &= 0xFF; else sra=~0 -> unchanged
                key[k] &= ((unsigned)((int)s >> 31)) | 0xFFu;
            }
        }
    }

    // farthest pair among 4 peaks: pack (d, 5-q, coords) into one u32 key
    unsigned kbest = 0;
    {
        const int pa[6] = {0, 0, 0, 1, 1, 2};
        const int pb[6] = {1, 2, 3, 2, 3, 3};
#pragma unroll
        for (int q = 0; q < 6; q++) {
            const int ax = px[pa[q]], ay = py[pa[q]];
            const int bx = px[pb[q]], by = py[pb[q]];
            const int dx = bx - ax, dy = by - ay;
            const int d  = dx * dx + dy * dy;           // <= 338 (9 bits)
            const unsigned kd = ((unsigned)d << 20) | ((unsigned)(5 - q) << 16)
                              | (unsigned)(ax | (ay << 4) | (bx << 8) | (by << 12));
            kbest = max(kbest, kd);
        }
    }
    const int ax = (int)(kbest & 0xFu);
    const int ay = (int)((kbest >> 4)  & 0xFu);
    const int bx = (int)((kbest >> 8)  & 0xFu);
    const int by = (int)((kbest >> 12) & 0xFu);

    // d1 - d2 = Cx*u + Cy*v - Cc  (all exact small-int floats)
    const int dxc = bx - ax, dyc = by - ay;
    const float Cx  = (float)(2 * dxc);
    const float Cy  = (float)(2 * dyc);
    const float mCc = (float)(-(dxc * (ax + bx) + dyc * (ay + by)));

    float* __restrict__ o1 = out + (size_t)warp * NPIX;
    float* __restrict__ o2 = o1 + (size_t)B * NPIX;

#pragma unroll
    for (int k = 0; k < 7; k++) {
        const bool live = (k < 6) || live6;
        if (live) {
            const int i = lane + 32 * k;
            const float pv = fmaf(Cx, feu[k], fmaf(Cy, fev[k], mCc));   // d1-d2
            const unsigned m1b = ((unsigned)((int)__float_as_uint(pv) >> 31)) & 0x3F800000u;
            o1[i] = __uint_as_float(m1b);                 // 1.0f if d1<d2 else 0.0f
            o2[i] = __uint_as_float(m1b ^ 0x3F800000u);   // complement
        }
    }
}

extern "C" void kernel_launch(void* const* d_in, const int* in_sizes, int n_in,
                              void* d_out, int out_size)
{
    const float* hm  = (const float*)d_in[0];
    float*       out = (float*)d_out;
    const int B = in_sizes[0] / NPIX;                    // 131072
    const int grid = (B + WPB - 1) / WPB;
    nms_masks_kernel<<<grid, THREADS>>>(hm, out, B);
}

// round 6
// speedup vs baseline: 1.3029x; 1.3029x over previous
#include <cuda_runtime.h>
#include <cstdint>

// NMS_20933670600803  — heatmap (B,1,14,14) f32 -> [m1 | m2] f32
//
// One warp per item. float4 I/O: lane j owns elements {4j..4j+3} and
// (j<17) {128+4j..128+4j+3}.
//
// Keys (validated in R4/R5, rel_err 0):
//   key = (max(fb, bits(0.6f)) << 8) + (0xE66666FF - i)   [mod 2^32]
//       = ((M - KTHR) << 8) | (255 - i)
// so below-threshold and suppressed elements share key = 255-i; unsigned max
// == (max value, tie -> smallest index) == jnp.argmax. Warp reduce = one
// REDUX.MAX.U32. Suppression = key &= 0xFF.
// Dead slots (i >= 196) load 0.0 -> key = 255-i <= 59 < 60 <= any live key.
//
// Suppression windows are precomputed: for each of 196 peak positions, the
// 196-bit window mask as 8 u32 words in __constant__ (constexpr-initialized).
// Per element the suppress test is SHF+SHF+LOP3 on a pre-shifted nibble.
//
// Voronoi: d1-d2 = Cx*eu + Cy*ev + mCc, all-integer IMAD; sign bit -> 1.0f.

#define NPIX 196
#define NVEC 49
#define WPB  8
#define THREADS (WPB * 32)
#define KTHR 0x3F19999Au     // __float_as_uint(0.6f)

struct MaskTable {
    unsigned w[196][8];
    constexpr MaskTable() : w{} {
        for (int bi = 0; bi < 196; ++bi) {
            int x = bi / 14, y = bi % 14;
            int x1 = (x - 5 > 0) ? x - 5 : 0;
            int x2 = (x + 5 < 15) ? x + 5 : 15;
            int y1 = (y - 5 > 0) ? y - 5 : 0;
            int y2 = (y + 5 < 15) ? y + 5 : 15;
            for (int i = 0; i < 196; ++i) {
                int eu = i / 14, ev = i % 14;
                if (eu >= x1 && eu < x2 && ev >= y1 && ev < y2)
                    w[bi][i >> 5] |= 1u << (i & 31);
            }
        }
    }
};
__constant__ MaskTable g_masks;   // constant-initialized (constexpr ctor)

__global__ __launch_bounds__(THREADS)
void nms_masks_kernel(const float4* __restrict__ hm,
                      float4* __restrict__ out,
                      int B)
{
    const int warp = blockIdx.x * WPB + (threadIdx.x >> 5);
    const int lane = threadIdx.x & 31;
    if (warp >= B) return;

    const float4* __restrict__ p = hm + (size_t)warp * NVEC;
    float4 va = p[lane];                       // elements 4j..4j+3 (4j+3 <= 127)
    const bool has2 = (lane < 17);
    float4 vb = make_float4(0.f, 0.f, 0.f, 0.f);
    if (has2) vb = p[lane + 32];               // elements 128+4j..

    const int i0 = 4 * lane;
    const int i1 = 128 + 4 * lane;

    unsigned key[8];
    {
        const float vals[8] = {va.x, va.y, va.z, va.w, vb.x, vb.y, vb.z, vb.w};
#pragma unroll
        for (int c = 0; c < 8; ++c) {
            const int i = (c < 4) ? (i0 + c) : (i1 + c - 4);
            const unsigned fb = __float_as_uint(vals[c]);
            const unsigned M  = (fb > KTHR) ? fb : KTHR;           // IMNMX.U32
            key[c] = M * 256u + (0xE66666FFu - (unsigned)i);       // IMAD, wraps ok
        }
    }

    const int h0 = lane >> 3;                  // word index of this lane's nibble
    const int sh = 28 - 4 * (lane & 7);        // shift nibble to bits [28..31]

    int px[4], py[4];

#pragma unroll
    for (int it = 0; it < 4; ++it) {
        unsigned m = max(max(max(key[0], key[1]), max(key[2], key[3])),
                         max(max(key[4], key[5]), max(key[6], key[7])));
        const unsigned w = __reduce_max_sync(0xffffffffu, m);      // REDUX.MAX.U32

        const int bi = 255 - (int)(w & 0xFFu);
        const int x  = (bi * 18725) >> 18;     // bi / 14 for bi < 256
        const int y  = bi - 14 * x;
        px[it] = x; py[it] = y;

        if (it < 3) {
            const unsigned* __restrict__ row = g_masks.w[bi];      // warp-uniform
            const unsigned t0 = row[h0]     << sh;                 // lower-half nibble at top
            const unsigned t1 = row[h0 + 4] << sh;                 // upper-half nibble at top
#pragma unroll
            for (int c = 0; c < 4; ++c) {
                const unsigned m0 = (unsigned)((int)(t0 << (3 - c)) >> 31);
                const unsigned m1 = (unsigned)((int)(t1 << (3 - c)) >> 31);
                key[c]     &= (~m0 | 0xFFu);   // single LOP3 each
                key[c + 4] &= (~m1 | 0xFFu);
            }
        }
    }

    // farthest pair among the 4 peaks (6 pairs, first-tie argmax), packed key
    unsigned kbest = 0;
    {
        const int pa[6] = {0, 0, 0, 1, 1, 2};
        const int pb[6] = {1, 2, 3, 2, 3, 3};
#pragma unroll
        for (int q = 0; q < 6; ++q) {
            const int qax = px[pa[q]], qay = py[pa[q]];
            const int qbx = px[pb[q]], qby = py[pb[q]];
            const int dx = qbx - qax, dy = qby - qay;
            const int d  = dx * dx + dy * dy;                      // <= 338
            const unsigned kd = ((unsigned)d << 20) | ((unsigned)(5 - q) << 16)
                              | (unsigned)(qax | (qay << 4) | (qbx << 8) | (qby << 12));
            kbest = (kbest > kd) ? kbest : kd;
        }
    }
    const int ax = (int)(kbest & 0xFu);
    const int ay = (int)((kbest >> 4)  & 0xFu);
    const int bx = (int)((kbest >> 8)  & 0xFu);
    const int by = (int)((kbest >> 12) & 0xFu);

    // d1 - d2 = Cx*eu + Cy*ev + mCc  (all small exact ints)
    const int dxc = bx - ax, dyc = by - ay;
    const int Cx  = 2 * dxc;
    const int Cy  = 2 * dyc;
    const int mCc = -(dxc * (ax + bx) + dyc * (ay + by));

    float4* __restrict__ o1 = out + (size_t)warp * NVEC;
    float4* __restrict__ o2 = o1 + (size_t)B * NVEC;

    float r1[4], r2[4];
#pragma unroll
    for (int c = 0; c < 4; ++c) {
        const int i  = i0 + c;
        const int eu = (i * 18725) >> 18;
        const int ev = i - 14 * eu;
        const int pv = Cx * eu + Cy * ev + mCc;                    // d1 - d2
        const unsigned m1b = ((unsigned)(pv >> 31)) & 0x3F800000u; // 1.0f if d1<d2
        r1[c] = __uint_as_float(m1b);
        r2[c] = __uint_as_float(m1b ^ 0x3F800000u);
    }
    o1[lane] = make_float4(r1[0], r1[1], r1[2], r1[3]);
    o2[lane] = make_float4(r2[0], r2[1], r2[2], r2[3]);

    if (has2) {
#pragma unroll
        for (int c = 0; c < 4; ++c) {
            const int i  = i1 + c;
            const int eu = (i * 18725) >> 18;
            const int ev = i - 14 * eu;
            const int pv = Cx * eu + Cy * ev + mCc;
            const unsigned m1b = ((unsigned)(pv >> 31)) & 0x3F800000u;
            r1[c] = __uint_as_float(m1b);
            r2[c] = __uint_as_float(m1b ^ 0x3F800000u);
        }
        o1[lane + 32] = make_float4(r1[0], r1[1], r1[2], r1[3]);
        o2[lane + 32] = make_float4(r2[0], r2[1], r2[2], r2[3]);
    }
}

extern "C" void kernel_launch(void* const* d_in, const int* in_sizes, int n_in,
                              void* d_out, int out_size)
{
    const float4* hm  = (const float4*)d_in[0];
    float4*       out = (float4*)d_out;
    const int B = in_sizes[0] / NPIX;          // 131072
    const int grid = (B + WPB - 1) / WPB;
    nms_masks_kernel<<<grid, THREADS>>>(hm, out, B);
}

// round 7
// speedup vs baseline: 1.3417x; 1.0298x over previous
#include <cuda_runtime.h>
#include <cstdint>

// NMS_20933670600803  — heatmap (B,1,14,14) f32 -> [m1 | m2] f32
//
// One warp per item, float4 I/O. Keys (validated R4-R6, rel_err 0):
//   key = (max(fb, bits(0.6f)) << 8) + (0xE66666FF - i)  [mod 2^32]
// below-threshold / suppressed -> key = 255 - i; unsigned max == jnp.argmax.
// Warp reduce = REDUX.MAX.U32; suppression = key &= 0xFF via constant table.
// Dead slots (i >= 196) load 0.0 -> key = 255-i <= 59 < 60 <= live keys.
//
// R7: uint2-interleaved mask table (LDC.64), ~w decode, deferred x/y decode,
// incremental pv emission, streaming ld/st hints.

#define NPIX 196
#define NVEC 49
#define WPB  8
#define THREADS (WPB * 32)
#define KTHR 0x3F19999Au     // __float_as_uint(0.6f)

struct alignas(8) MaskTable {
    // interleaved: w[bi][2h+0] = window word h, w[bi][2h+1] = window word h+4
    unsigned w[196][8];
    constexpr MaskTable() : w{} {
        for (int bi = 0; bi < 196; ++bi) {
            int x = bi / 14, y = bi % 14;
            int x1 = (x - 5 > 0) ? x - 5 : 0;
            int x2 = (x + 5 < 15) ? x + 5 : 15;
            int y1 = (y - 5 > 0) ? y - 5 : 0;
            int y2 = (y + 5 < 15) ? y + 5 : 15;
            unsigned full[8] = {};
            for (int i = 0; i < 196; ++i) {
                int eu = i / 14, ev = i % 14;
                if (eu >= x1 && eu < x2 && ev >= y1 && ev < y2)
                    full[i >> 5] |= 1u << (i & 31);
            }
            for (int h = 0; h < 4; ++h) {
                w[bi][2 * h]     = full[h];
                w[bi][2 * h + 1] = full[h + 4];
            }
        }
    }
};
__constant__ MaskTable g_masks;

__global__ __launch_bounds__(THREADS)
void nms_masks_kernel(const float4* __restrict__ hm,
                      float4* __restrict__ out,
                      int B)
{
    const int warp = blockIdx.x * WPB + (threadIdx.x >> 5);
    const int lane = threadIdx.x & 31;
    if (warp >= B) return;

    const float4* __restrict__ p = hm + (size_t)warp * NVEC;
    const float4 va = __ldcs(p + lane);            // elements 4j..4j+3
    const bool has2 = (lane < 17);
    float4 vb = make_float4(0.f, 0.f, 0.f, 0.f);
    if (has2) vb = __ldcs(p + lane + 32);          // elements 128+4j..

    const int i0 = 4 * lane;
    const int i1 = 128 + 4 * lane;

    unsigned key[8];
    {
        const float vals[8] = {va.x, va.y, va.z, va.w, vb.x, vb.y, vb.z, vb.w};
#pragma unroll
        for (int c = 0; c < 8; ++c) {
            const int i = (c < 4) ? (i0 + c) : (i1 + c - 4);
            const unsigned fb = __float_as_uint(vals[c]);
            const unsigned M  = (fb > KTHR) ? fb : KTHR;          // IMNMX.U32
            key[c] = M * 256u + (0xE66666FFu - (unsigned)i);      // IMAD, wraps ok
        }
    }

    const int h2 = (lane >> 3) * 2;                // interleaved word pair index
    const int sh = 28 - 4 * (lane & 7);            // shift nibble to bits [28..31]

    int bis[4];
#pragma unroll
    for (int it = 0; it < 4; ++it) {
        unsigned m = max(max(max(key[0], key[1]), max(key[2], key[3])),
                         max(max(key[4], key[5]), max(key[6], key[7])));
        const unsigned w = __reduce_max_sync(0xffffffffu, m);     // REDUX.MAX.U32
        const int bi = (int)((~w) & 0xFFu);                       // 255 - (w & 0xFF)
        bis[it] = bi;

        if (it < 3) {
            const uint2 t = *reinterpret_cast<const uint2*>(&g_masks.w[bi][h2]);
            const unsigned t0 = t.x << sh;         // lower-half nibble at top
            const unsigned t1 = t.y << sh;         // upper-half nibble at top
#pragma unroll
            for (int c = 0; c < 4; ++c) {
                const unsigned m0 = (unsigned)((int)(t0 << (3 - c)) >> 31);
                const unsigned m1 = (unsigned)((int)(t1 << (3 - c)) >> 31);
                key[c]     &= (~m0 | 0xFFu);       // single LOP3 each
                key[c + 4] &= (~m1 | 0xFFu);
            }
        }
    }

    // decode peaks once, after the loop (off the REDUX->LDC critical path)
    int px[4], py[4], pk[4];
#pragma unroll
    for (int t = 0; t < 4; ++t) {
        const int x = (bis[t] * 18725) >> 18;      // bi / 14 for bi < 256
        const int y = bis[t] - 14 * x;
        px[t] = x; py[t] = y; pk[t] = x | (y << 4);
    }

    // farthest pair among 4 peaks (6 pairs, first-tie argmax), packed key
    unsigned kbest = 0;
    {
        const int pa[6] = {0, 0, 0, 1, 1, 2};
        const int pb[6] = {1, 2, 3, 2, 3, 3};
#pragma unroll
        for (int q = 0; q < 6; ++q) {
            const int dx = px[pb[q]] - px[pa[q]];
            const int dy = py[pb[q]] - py[pa[q]];
            const int d  = dx * dx + dy * dy;      // <= 338
            const unsigned kd = ((unsigned)d << 20) | ((unsigned)(5 - q) << 16)
                              | (unsigned)(pk[pa[q]] | (pk[pb[q]] << 8));
            kbest = (kbest > kd) ? kbest : kd;
        }
    }
    const int ax = (int)(kbest & 0xFu);
    const int ay = (int)((kbest >> 4)  & 0xFu);
    const int bx = (int)((kbest >> 8)  & 0xFu);
    const int by = (int)((kbest >> 12) & 0xFu);

    // d1 - d2 = Cx*eu + Cy*ev + mCc = Cy*i + Cg*eu + mCc  (ev = i - 14*eu)
    const int dxc = bx - ax, dyc = by - ay;
    const int Cy  = 2 * dyc;
    const int Cg  = 2 * dxc - 14 * Cy;
    const int mCc = -(dxc * (ax + bx) + dyc * (ay + by));

    float4* __restrict__ o1 = out + (size_t)warp * NVEC;
    float4* __restrict__ o2 = o1 + (size_t)B * NVEC;

    {
        float r1[4], r2[4];
        int s = Cy * i0 + mCc;
#pragma unroll
        for (int c = 0; c < 4; ++c) {
            const int i  = i0 + c;
            const int eu = (i * 18725) >> 18;
            const int pv = s + Cg * eu;            // d1 - d2
            s += Cy;
            const unsigned m1b = ((unsigned)(pv >> 31)) & 0x3F800000u;
            r1[c] = __uint_as_float(m1b);                 // 1.0f if d1<d2
            r2[c] = __uint_as_float(m1b ^ 0x3F800000u);   // complement
        }
        __stcs(o1 + lane, make_float4(r1[0], r1[1], r1[2], r1[3]));
        __stcs(o2 + lane, make_float4(r2[0], r2[1], r2[2], r2[3]));
    }
    if (has2) {
        float r1[4], r2[4];
        int s = Cy * i1 + mCc;
#pragma unroll
        for (int c = 0; c < 4; ++c) {
            const int i  = i1 + c;
            const int eu = (i * 18725) >> 18;
            const int pv = s + Cg * eu;
            s += Cy;
            const unsigned m1b = ((unsigned)(pv >> 31)) & 0x3F800000u;
            r1[c] = __uint_as_float(m1b);
            r2[c] = __uint_as_float(m1b ^ 0x3F800000u);
        }
        __stcs(o1 + lane + 32, make_float4(r1[0], r1[1], r1[2], r1[3]));
        __stcs(o2 + lane + 32, make_float4(r2[0], r2[1], r2[2], r2[3]));
    }
}

extern "C" void kernel_launch(void* const* d_in, const int* in_sizes, int n_in,
                              void* d_out, int out_size)
{
    const float4* hm  = (const float4*)d_in[0];
    float4*       out = (float4*)d_out;
    const int B = in_sizes[0] / NPIX;              // 131072
    const int grid = (B + WPB - 1) / WPB;
    nms_masks_kernel<<<grid, THREADS>>>(hm, out, B);
}